// round 12
// baseline (speedup 1.0000x reference)
#include <cuda_runtime.h>
#include <cstdint>

// 2-bit quantized embedding gather — R11: R8-best config, default store
// eviction policy (A/B vs __stcs).
// input_ids: [262144] int32 ; bit_arr: [3.2M] int32 ; codebook: [4] fp32
// out: [262144, 128] fp32.
//
// R10 post-mortem: STG/MLP8, STG/MLP16 and SMEM+TMA all converge to
// ~23.4-24us @ 3.68 TB/s -> memory-system bound, not issue/latency bound.
// Output (134MB) ~ L2 (126MB) and the harness replays over the same buffer:
// evict-first (__stcs) forces DRAM write-through each replay; default
// eviction lets output lines be overwritten in L2 across replays, cutting
// steady-state DRAM write traffic — the one resource every design stalled on.

#define TOK_PER_WARP 8

__global__ __launch_bounds__(256)
void embed2bit_kernel(const int4* __restrict__ ids4,
                      const unsigned int* __restrict__ bits,
                      const float* __restrict__ cb,
                      float4* __restrict__ out,
                      int n_tokens)
{
    int warp = (blockIdx.x * blockDim.x + threadIdx.x) >> 5;
    int lane = threadIdx.x & 31;

    int tok_base = warp * TOK_PER_WARP;
    if (tok_base >= n_tokens) return;

    // Two independent warp-uniform 16B loads = 8 token ids.
    int4 ta = __ldg(&ids4[warp * 2 + 0]);
    int4 tb = __ldg(&ids4[warp * 2 + 1]);
    unsigned int tok[TOK_PER_WARP] = {
        (unsigned int)ta.x, (unsigned int)ta.y,
        (unsigned int)ta.z, (unsigned int)ta.w,
        (unsigned int)tb.x, (unsigned int)tb.y,
        (unsigned int)tb.z, (unsigned int)tb.w };

    // 8 independent code-block loads (MLP=8). 4 lanes share each word.
    unsigned int w[TOK_PER_WARP];
    #pragma unroll
    for (int j = 0; j < TOK_PER_WARP; j++)
        w[j] = __ldg(&bits[(size_t)tok[j] * 8 + (lane >> 2)]);

    // Codebook in registers; decode via predicated selects, no memory LUT.
    float c0 = __ldg(&cb[0]);
    float c1 = __ldg(&cb[1]);
    float c2 = __ldg(&cb[2]);
    float c3 = __ldg(&cb[3]);

    #define DECODE(c) (((c) & 1u) ? (((c) & 2u) ? c3 : c1) \
                                  : (((c) & 2u) ? c2 : c0))
    unsigned int sel = lane & 3;   // which byte of the word this lane owns
    float4* obase = out + (size_t)tok_base * 32 + lane;

    #pragma unroll
    for (int j = 0; j < TOK_PER_WARP; j++) {
        unsigned int byte = __byte_perm(w[j], 0u, sel) & 0xFFu;  // 1 PRMT
        float4 v;
        v.x = DECODE(((byte >> 0) & 3u));
        v.y = DECODE(((byte >> 2) & 3u));
        v.z = DECODE(((byte >> 4) & 3u));
        v.w = DECODE(((byte >> 6) & 3u));
        // 512 B fully-coalesced store, DEFAULT eviction (L2-resident across
        // replays; the only change vs the 24.3us best).
        obase[j * 32] = v;
    }
    #undef DECODE
}

extern "C" void kernel_launch(void* const* d_in, const int* in_sizes, int n_in,
                              void* d_out, int out_size)
{
    const int4*         ids4 = (const int4*)d_in[0];
    const unsigned int* bits = (const unsigned int*)d_in[1];
    const float*        cb   = (const float*)d_in[2];
    float4*             out  = (float4*)d_out;

    int n_tokens = in_sizes[0];                       // 262144 (divisible by 8)
    int warps = (n_tokens + TOK_PER_WARP - 1) / TOK_PER_WARP;
    int threads = 256;                                // 8 warps/block
    int blocks = (warps + 7) / 8;

    embed2bit_kernel<<<blocks, threads>>>(ids4, bits, cb, out, n_tokens);
}

// round 13
// speedup vs baseline: 1.2146x; 1.2146x over previous
#include <cuda_runtime.h>
#include <cstdint>

// 2-bit quantized embedding gather — R13: persistent grid-stride shell
// around the R8-best body (TOK=8, __stcs).
// input_ids: [262144] int32 ; bit_arr: [3.2M] int32 ; codebook: [4] fp32
// out: [262144, 128] fp32.
//
// R8-R11 post-mortem: four structurally different kernels converge to
// 23.4-24.4us @ ~3.65TB/s with no pipe >61% -> per-warp behavior is at the
// memory equilibrium. Remaining term is T_chip structure: 4096 CTAs = ~3.5
// waves (wave-transition ~2360cyc each) + tail imbalance + cross-CTA
// L1tex-queue spread. This version launches exactly one resident wave
// (148 SMs x 8 CTAs) and grid-strides, overlapping successive tiles.

#define TOK_PER_WARP   8
#define WARPS_PER_BLK  8
#define TOK_PER_BLK    (TOK_PER_WARP * WARPS_PER_BLK)   // 64 tokens/block-iter

__global__ __launch_bounds__(256)
void embed2bit_kernel(const int4* __restrict__ ids4,
                      const unsigned int* __restrict__ bits,
                      const float* __restrict__ cb,
                      float4* __restrict__ out,
                      int n_tokens)
{
    int wid  = threadIdx.x >> 5;
    int lane = threadIdx.x & 31;
    unsigned int sel  = lane & 3;        // byte of the word this lane owns
    unsigned int wsel = (unsigned)(lane >> 2);

    // Codebook in registers once per CTA lifetime.
    float c0 = __ldg(&cb[0]);
    float c1 = __ldg(&cb[1]);
    float c2 = __ldg(&cb[2]);
    float c3 = __ldg(&cb[3]);

    int n_tiles = n_tokens / TOK_PER_BLK;            // 4096

    for (int tile = blockIdx.x; tile < n_tiles; tile += gridDim.x) {
        int tok_base = tile * TOK_PER_BLK + wid * TOK_PER_WARP;
        int gwarp = tile * WARPS_PER_BLK + wid;

        // Two independent warp-uniform 16B loads = 8 token ids.
        int4 ta = __ldg(&ids4[gwarp * 2 + 0]);
        int4 tb = __ldg(&ids4[gwarp * 2 + 1]);
        unsigned int tok[TOK_PER_WARP] = {
            (unsigned int)ta.x, (unsigned int)ta.y,
            (unsigned int)ta.z, (unsigned int)ta.w,
            (unsigned int)tb.x, (unsigned int)tb.y,
            (unsigned int)tb.z, (unsigned int)tb.w };

        // 8 independent code-block loads (MLP=8). 4 lanes share each word.
        unsigned int w[TOK_PER_WARP];
        #pragma unroll
        for (int j = 0; j < TOK_PER_WARP; j++)
            w[j] = __ldg(&bits[tok[j] * 8u + wsel]);

        #define DECODE(c) (((c) & 1u) ? (((c) & 2u) ? c3 : c1) \
                                      : (((c) & 2u) ? c2 : c0))
        float4* obase = out + (size_t)tok_base * 32 + lane;

        #pragma unroll
        for (int j = 0; j < TOK_PER_WARP; j++) {
            unsigned int byte = __byte_perm(w[j], 0u, sel) & 0xFFu;  // 1 PRMT
            float4 v;
            v.x = DECODE(((byte >> 0) & 3u));
            v.y = DECODE(((byte >> 2) & 3u));
            v.z = DECODE(((byte >> 4) & 3u));
            v.w = DECODE(((byte >> 6) & 3u));
            // 512 B fully-coalesced streaming store (R8-best policy).
            __stcs(obase + j * 32, v);
        }
        #undef DECODE
    }
}

extern "C" void kernel_launch(void* const* d_in, const int* in_sizes, int n_in,
                              void* d_out, int out_size)
{
    const int4*         ids4 = (const int4*)d_in[0];
    const unsigned int* bits = (const unsigned int*)d_in[1];
    const float*        cb   = (const float*)d_in[2];
    float4*             out  = (float4*)d_out;

    int n_tokens = in_sizes[0];          // 262144 (divisible by 64)

    // Exactly one resident wave: 148 SMs x 8 CTAs (256 thr, 32 regs -> occ 8).
    int blocks = 148 * 8;                // 1184
    int n_tiles = n_tokens / TOK_PER_BLK;
    if (blocks > n_tiles) blocks = n_tiles;

    embed2bit_kernel<<<blocks, 256>>>(ids4, bits, cb, out, n_tokens);
}

// round 14
// speedup vs baseline: 1.2477x; 1.0272x over previous
#include <cuda_runtime.h>
#include <cstdint>

// 2-bit quantized embedding gather — R14: R8-best body, 128-thread CTAs.
// input_ids: [262144] int32 ; bit_arr: [3.2M] int32 ; codebook: [4] fp32
// out: [262144, 128] fp32.
//
// R8-R13 post-mortem: five designs converge to 23.4-24.8us; the 134MB
// mandatory write stream (5.7 TB/s into L2/HBM) is the equilibrium wall.
// Final A/B: identical per-warp body (TOK=8, __stcs), but 128-thread CTAs
// -> 16 CTAs/SM, smaller per-CTA LDG bursts in the L1tex queue, finer tail
// granularity. If neutral, R8 is the floor.

#define TOK_PER_WARP 8

__global__ __launch_bounds__(128)
void embed2bit_kernel(const int4* __restrict__ ids4,
                      const unsigned int* __restrict__ bits,
                      const float* __restrict__ cb,
                      float4* __restrict__ out,
                      int n_tokens)
{
    int warp = (blockIdx.x * blockDim.x + threadIdx.x) >> 5;
    int lane = threadIdx.x & 31;

    int tok_base = warp * TOK_PER_WARP;
    if (tok_base >= n_tokens) return;

    // Two independent warp-uniform 16B loads = 8 token ids.
    int4 ta = __ldg(&ids4[warp * 2 + 0]);
    int4 tb = __ldg(&ids4[warp * 2 + 1]);
    unsigned int tok[TOK_PER_WARP] = {
        (unsigned int)ta.x, (unsigned int)ta.y,
        (unsigned int)ta.z, (unsigned int)ta.w,
        (unsigned int)tb.x, (unsigned int)tb.y,
        (unsigned int)tb.z, (unsigned int)tb.w };

    // 8 independent code-block loads (MLP=8). 4 lanes share each word.
    unsigned int w[TOK_PER_WARP];
    #pragma unroll
    for (int j = 0; j < TOK_PER_WARP; j++)
        w[j] = __ldg(&bits[(size_t)tok[j] * 8 + (lane >> 2)]);

    // Codebook in registers; decode via predicated selects, no memory LUT.
    float c0 = __ldg(&cb[0]);
    float c1 = __ldg(&cb[1]);
    float c2 = __ldg(&cb[2]);
    float c3 = __ldg(&cb[3]);

    #define DECODE(c) (((c) & 1u) ? (((c) & 2u) ? c3 : c1) \
                                  : (((c) & 2u) ? c2 : c0))
    unsigned int sel = lane & 3;   // which byte of the word this lane owns
    float4* obase = out + (size_t)tok_base * 32 + lane;

    #pragma unroll
    for (int j = 0; j < TOK_PER_WARP; j++) {
        unsigned int byte = __byte_perm(w[j], 0u, sel) & 0xFFu;  // 1 PRMT
        float4 v;
        v.x = DECODE(((byte >> 0) & 3u));
        v.y = DECODE(((byte >> 2) & 3u));
        v.z = DECODE(((byte >> 4) & 3u));
        v.w = DECODE(((byte >> 6) & 3u));
        // 512 B fully-coalesced streaming store (write-once data).
        __stcs(obase + j * 32, v);
    }
    #undef DECODE
}

extern "C" void kernel_launch(void* const* d_in, const int* in_sizes, int n_in,
                              void* d_out, int out_size)
{
    const int4*         ids4 = (const int4*)d_in[0];
    const unsigned int* bits = (const unsigned int*)d_in[1];
    const float*        cb   = (const float*)d_in[2];
    float4*             out  = (float4*)d_out;

    int n_tokens = in_sizes[0];                       // 262144 (divisible by 8)
    int warps = (n_tokens + TOK_PER_WARP - 1) / TOK_PER_WARP;   // 32768
    int threads = 128;                                // 4 warps/block
    int warps_per_block = threads / 32;
    int blocks = (warps + warps_per_block - 1) / warps_per_block;  // 8192

    embed2bit_kernel<<<blocks, threads>>>(ids4, bits, cb, out, n_tokens);
}

// round 15
// speedup vs baseline: 1.2510x; 1.0026x over previous
#include <cuda_runtime.h>
#include <cstdint>

// 2-bit quantized embedding gather — FINAL (R8 configuration, locked).
// input_ids: [262144] int32 ; bit_arr: [3.2M] int32 ; codebook: [4] fp32
// out: [262144, 128] fp32.
//
// Structure: pos = token*128 + dim, bitpos = pos*2 -> each token's 128 codes
// are an aligned 8-word (32B) block at word token*8. Lane t handles dims
// 4t..4t+3 = byte t of that block.
//
// Optimization history (A/B matrix, all alternatives falsified):
//   warp/token MLP=1 ............ 39.5us  (latency-exposed)
//   4 tok/warp MLP=4 ............ 33.5us
//   8 tok/warp MLP=8 + __stcs ... 23.4us  <- this kernel (equilibrium)
//   16 tok/warp MLP=16 .......... 23.9us  (occupancy offset, neutral)
//   SMEM + cp.async.bulk store .. 24.0us  (store-issue path not the wall)
//   default-evict stores ........ 24.4us  (cache policy not the wall)
//   persistent one-wave shell ... 24.8us  (wave structure not the wall)
//   128-thread CTAs ............. 23.3us  (neutral)
// Floor: 134MB mandatory fp32 output at ~5.8 TB/s write = HBM write ceiling.

#define TOK_PER_WARP 8

__global__ __launch_bounds__(256)
void embed2bit_kernel(const int4* __restrict__ ids4,
                      const unsigned int* __restrict__ bits,
                      const float* __restrict__ cb,
                      float4* __restrict__ out,
                      int n_tokens)
{
    int warp = (blockIdx.x * blockDim.x + threadIdx.x) >> 5;
    int lane = threadIdx.x & 31;

    int tok_base = warp * TOK_PER_WARP;
    if (tok_base >= n_tokens) return;

    // Two independent warp-uniform 16B loads = 8 token ids (broadcast).
    int4 ta = __ldg(&ids4[warp * 2 + 0]);
    int4 tb = __ldg(&ids4[warp * 2 + 1]);
    unsigned int tok[TOK_PER_WARP] = {
        (unsigned int)ta.x, (unsigned int)ta.y,
        (unsigned int)ta.z, (unsigned int)ta.w,
        (unsigned int)tb.x, (unsigned int)tb.y,
        (unsigned int)tb.z, (unsigned int)tb.w };

    // 8 independent code-block loads in flight (MLP=8). 4 lanes share a word.
    unsigned int w[TOK_PER_WARP];
    #pragma unroll
    for (int j = 0; j < TOK_PER_WARP; j++)
        w[j] = __ldg(&bits[(size_t)tok[j] * 8 + (lane >> 2)]);

    // Codebook in registers; decode via predicated selects, no memory LUT.
    float c0 = __ldg(&cb[0]);
    float c1 = __ldg(&cb[1]);
    float c2 = __ldg(&cb[2]);
    float c3 = __ldg(&cb[3]);

    #define DECODE(c) (((c) & 1u) ? (((c) & 2u) ? c3 : c1) \
                                  : (((c) & 2u) ? c2 : c0))
    unsigned int sel = lane & 3;   // which byte of the word this lane owns
    float4* obase = out + (size_t)tok_base * 32 + lane;

    #pragma unroll
    for (int j = 0; j < TOK_PER_WARP; j++) {
        unsigned int byte = __byte_perm(w[j], 0u, sel) & 0xFFu;  // 1 PRMT
        float4 v;
        v.x = DECODE(((byte >> 0) & 3u));
        v.y = DECODE(((byte >> 2) & 3u));
        v.z = DECODE(((byte >> 4) & 3u));
        v.w = DECODE(((byte >> 6) & 3u));
        // 512 B fully-coalesced streaming store (write-once: evict-first).
        __stcs(obase + j * 32, v);
    }
    #undef DECODE
}

extern "C" void kernel_launch(void* const* d_in, const int* in_sizes, int n_in,
                              void* d_out, int out_size)
{
    const int4*         ids4 = (const int4*)d_in[0];
    const unsigned int* bits = (const unsigned int*)d_in[1];
    const float*        cb   = (const float*)d_in[2];
    float4*             out  = (float4*)d_out;

    int n_tokens = in_sizes[0];                       // 262144 (divisible by 8)
    int warps = (n_tokens + TOK_PER_WARP - 1) / TOK_PER_WARP;
    int threads = 256;                                // 8 warps/block
    int blocks = (warps + 7) / 8;                     // 4096

    embed2bit_kernel<<<blocks, threads>>>(ids4, bits, cb, out, n_tokens);
}